// round 1
// baseline (speedup 1.0000x reference)
#include <cuda_runtime.h>
#include <cuda_bf16.h>
#include <cstdint>

// ---------------------------------------------------------------------------
// LSTM autoencoder: 6 LSTM layers (H = 512,256,128,128,256,512) over T=8192,
// final linear projection to 1 feature.
//
// Strategy:
//   - xg = X @ Wih^T + (bih+bhh) precomputed per layer with a tiled SGEMM
//     (parallel over all timesteps).
//   - The serial recurrence runs in a persistent multi-CTA scan kernel:
//     recurrent weights live in REGISTERS (spread over B CTAs), h is
//     double-buffered in global memory, CTAs synchronize each step with a
//     per-CTA flag array (single-wave grid, deadlock-free).
// ---------------------------------------------------------------------------

#define T_SEQ 8192

// Scratch (device globals; no dynamic allocation allowed).
__device__ float g_xg [T_SEQ * 2048];   // 64 MB, xg buffer (max 4H = 2048)
__device__ float g_ysA[T_SEQ * 512];    // 16 MB, layer-output ping
__device__ float g_ysB[T_SEQ * 512];    // 16 MB, layer-output pong
__device__ float g_h  [2 * 512];        // double-buffered hidden state
__device__ float g_gvec[2048];          // constant xg row for decoder layer d1
__device__ unsigned g_flags[6 * 64];    // per-layer CTA arrival flags

// ---------------------------------------------------------------------------
// Helpers
// ---------------------------------------------------------------------------
__device__ __forceinline__ float sigmoid_f(float x) {
    // 1/(1+e^-x); e^-x -> inf for very negative x gives 0, which is correct.
    return __fdividef(1.0f, 1.0f + __expf(-x));
}
__device__ __forceinline__ float tanh_f(float x) {
    x = fminf(fmaxf(x, -15.0f), 15.0f);
    float e = __expf(-2.0f * x);
    return __fdividef(1.0f - e, 1.0f + e);
}

// ---------------------------------------------------------------------------
// Reset per-launch state (flags). h/c are initialized inside the scan kernel.
// ---------------------------------------------------------------------------
__global__ void reset_flags_kernel() {
    int i = threadIdx.x;
    if (i < 6 * 64) g_flags[i] = 0u;
}

// ---------------------------------------------------------------------------
// xg for layer e1 (in_dim = 1): xg[t][g] = x[t]*Wih[g] + bih[g] + bhh[g]
// ---------------------------------------------------------------------------
__global__ void xg_e1_kernel(const float* __restrict__ x,
                             const float* __restrict__ Wih,
                             const float* __restrict__ bih,
                             const float* __restrict__ bhh) {
    int idx = blockIdx.x * blockDim.x + threadIdx.x;   // over T*2048
    int t = idx >> 11;
    int g = idx & 2047;
    g_xg[idx] = x[t] * Wih[g] + bih[g] + bhh[g];
}

// ---------------------------------------------------------------------------
// Tiled SGEMM: g_xg[M,N] = A[M,K] @ W[N,K]^T + (b1+b2)[N]
// M = 8192 fixed. BM=BN=64, BK=16, 256 threads, 4x4 micro-tile.
// A is selected from g_ysA / g_ysB by a_sel.
// ---------------------------------------------------------------------------
__global__ void __launch_bounds__(256) gemm_bias_kernel(
        int a_sel,
        const float* __restrict__ W,
        const float* __restrict__ b1,
        const float* __restrict__ b2,
        int N, int K) {
    const float* A = a_sel ? g_ysB : g_ysA;
    __shared__ float As[16][68];
    __shared__ float Ws[16][68];

    int tid = threadIdx.x;
    int bx = blockIdx.x;   // over N
    int by = blockIdx.y;   // over M
    int tx = tid & 15;
    int ty = tid >> 4;

    int lr = tid >> 2;          // 0..63 tile row
    int lc = (tid & 3) * 4;     // k offset 0,4,8,12

    const float* Ag = A + (size_t)(by * 64 + lr) * K + lc;
    const float* Wg = W + (size_t)(bx * 64 + lr) * K + lc;

    float acc[4][4] = {};

    for (int k0 = 0; k0 < K; k0 += 16) {
        float4 av = *(const float4*)(Ag + k0);
        float4 wv = *(const float4*)(Wg + k0);
        As[lc + 0][lr] = av.x; As[lc + 1][lr] = av.y;
        As[lc + 2][lr] = av.z; As[lc + 3][lr] = av.w;
        Ws[lc + 0][lr] = wv.x; Ws[lc + 1][lr] = wv.y;
        Ws[lc + 2][lr] = wv.z; Ws[lc + 3][lr] = wv.w;
        __syncthreads();
#pragma unroll
        for (int k = 0; k < 16; ++k) {
            float a[4], w4[4];
#pragma unroll
            for (int i = 0; i < 4; ++i) a[i]  = As[k][ty * 4 + i];
#pragma unroll
            for (int j = 0; j < 4; ++j) w4[j] = Ws[k][tx * 4 + j];
#pragma unroll
            for (int i = 0; i < 4; ++i)
#pragma unroll
                for (int j = 0; j < 4; ++j)
                    acc[i][j] += a[i] * w4[j];
        }
        __syncthreads();
    }

    int n0 = bx * 64 + tx * 4;
    float bs[4];
#pragma unroll
    for (int j = 0; j < 4; ++j) bs[j] = b1[n0 + j] + b2[n0 + j];
#pragma unroll
    for (int i = 0; i < 4; ++i) {
        int m = by * 64 + ty * 4 + i;
        float4 o = make_float4(acc[i][0] + bs[0], acc[i][1] + bs[1],
                               acc[i][2] + bs[2], acc[i][3] + bs[3]);
        *(float4*)&g_xg[(size_t)m * N + n0] = o;
    }
}

// ---------------------------------------------------------------------------
// gvec for d1: the decoder input is the SAME latent z for every timestep, so
// the input contribution is one row: gvec[n] = z @ Wih[n,:]^T + b1[n] + b2[n].
// z = last row of g_ysA (H=128 layout).
// ---------------------------------------------------------------------------
__global__ void gemv_d1_kernel(const float* __restrict__ Wih,
                               const float* __restrict__ b1,
                               const float* __restrict__ b2) {
    int n = blockIdx.x * blockDim.x + threadIdx.x;
    if (n >= 512) return;
    const float* z = g_ysA + (size_t)(T_SEQ - 1) * 128;
    float s = b1[n] + b2[n];
    const float* w = Wih + (size_t)n * 128;
#pragma unroll
    for (int k = 0; k < 128; k += 4) {
        float4 zv = *(const float4*)(z + k);
        float4 wv = *(const float4*)(w + k);
        s += zv.x * wv.x + zv.y * wv.y + zv.z * wv.z + zv.w * wv.w;
    }
    g_gvec[n] = s;
}

// ---------------------------------------------------------------------------
// Persistent sequential LSTM scan.
//   Grid: B = H/16 CTAs, 512 threads each (single wave, co-resident).
//   Each CTA owns U=16 hidden units -> ROWS=64 rows of Whh (i,f,g,o gates).
//   Thread (kseg = tid/64, row = tid%64) holds KLEN = H/8 weights in regs.
//   Per step: gmem flag barrier; read h (L2, __ldcg); register matvec;
//   smem reduce over 8 k-segments; 16 threads do gates + state update;
//   write h slice (double buffer) + ys[t]; set flag.
// ---------------------------------------------------------------------------
template <int H>
__global__ void __launch_bounds__(512, 1) lstm_scan_kernel(
        const float* __restrict__ Whh,   // [4H, H]
        int xg_sel,                       // 0: g_xg, 1: g_gvec
        int xg_stride,                    // 4H or 0
        int ys_sel,                       // 0: g_ysA, 1: g_ysB
        int flag_off) {
    constexpr int U = 16;
    constexpr int KSEG = 8;
    constexpr int KLEN = H / KSEG;
    constexpr int B = H / U;

    const float* xgp = xg_sel ? g_gvec : g_xg;
    float* ys = ys_sel ? g_ysB : g_ysA;
    unsigned* flags = g_flags + flag_off;
    volatile unsigned* vflags = (volatile unsigned*)flags;

    const int b   = blockIdx.x;
    const int tid = threadIdx.x;
    const int kseg = tid >> 6;     // 0..7
    const int row  = tid & 63;     // 0..63
    const int gate = row >> 4;     // 0..3 (i,f,g,o)
    const int unit = row & 15;     // 0..15
    const int grow = gate * H + b * U + unit;   // global Whh row
    const int kbase = kseg * KLEN;

    // Load this thread's weight slice into registers.
    float w[KLEN];
    {
        const float* wp = Whh + (size_t)grow * H + kbase;
#pragma unroll
        for (int i = 0; i < KLEN; i += 4) {
            float4 v = *(const float4*)(wp + i);
            w[i] = v.x; w[i + 1] = v.y; w[i + 2] = v.z; w[i + 3] = v.w;
        }
    }

    __shared__ float red[KSEG][64];
    __shared__ float garr[64];

    float c = 0.0f;   // cell state (live in threads tid < U)

    // init h0 = 0 in parity-0 buffer, then signal readiness (flag = 1).
    if (tid < U) g_h[b * U + tid] = 0.0f;
    __syncthreads();
    if (tid == 0) {
        __threadfence();
        atomicExch(&flags[b], 1u);
    }

    for (int t = 0; t < T_SEQ; ++t) {
        // Prefetch xg[t] BEFORE the barrier (no dependence on h).
        float xval = 0.0f;
        if (tid < 64) xval = xgp[(size_t)t * xg_stride + grow];

        // Wait for all CTAs to have published h_t.
        if (tid < B) {
            while (vflags[tid] < (unsigned)(t + 1)) { }
        }
        __syncthreads();

        // matvec partial: acc = sum_k w[k] * h[kbase+k]
        const float* hb = g_h + (t & 1) * H + kbase;
        float acc = 0.0f;
#pragma unroll
        for (int i = 0; i < KLEN; i += 4) {
            float4 hv = __ldcg((const float4*)(hb + i));
            acc += w[i] * hv.x + w[i + 1] * hv.y
                 + w[i + 2] * hv.z + w[i + 3] * hv.w;
        }
        red[kseg][row] = acc;
        __syncthreads();

        if (tid < 64) {
            float s = xval;
#pragma unroll
            for (int sgi = 0; sgi < KSEG; ++sgi) s += red[sgi][tid];
            garr[tid] = s;
        }
        __syncthreads();

        if (tid < U) {
            float gi = garr[tid];
            float gf = garr[U + tid];
            float gg = garr[2 * U + tid];
            float go = garr[3 * U + tid];
            float i_ = sigmoid_f(gi);
            float f_ = sigmoid_f(gf);
            float g_ = tanh_f(gg);
            float o_ = sigmoid_f(go);
            c = f_ * c + i_ * g_;
            float h = o_ * tanh_f(c);
            g_h[((t + 1) & 1) * H + b * U + tid] = h;
            ys[(size_t)t * H + b * U + tid] = h;
        }
        __syncthreads();
        if (tid == 0) {
            __threadfence();
            atomicExch(&flags[b], (unsigned)(t + 2));
        }
    }
}

// ---------------------------------------------------------------------------
// Final projection: out[t] = ys_d3[t,:] . out_W + out_b   (one warp per row)
// ---------------------------------------------------------------------------
__global__ void out_proj_kernel(const float* __restrict__ w,
                                const float* __restrict__ bias,
                                float* __restrict__ out) {
    int gtid = blockIdx.x * blockDim.x + threadIdx.x;
    int warp = gtid >> 5;
    int lane = threadIdx.x & 31;
    if (warp >= T_SEQ) return;
    const float* y = g_ysB + (size_t)warp * 512;
    float s = 0.0f;
#pragma unroll
    for (int j = 0; j < 16; ++j) {
        s += y[lane + 32 * j] * w[lane + 32 * j];
    }
#pragma unroll
    for (int off = 16; off > 0; off >>= 1)
        s += __shfl_down_sync(0xffffffffu, s, off);
    if (lane == 0) out[warp] = s + bias[0];
}

// ---------------------------------------------------------------------------
// Launch sequence (graph-capturable: kernel launches only)
// ---------------------------------------------------------------------------
extern "C" void kernel_launch(void* const* d_in, const int* in_sizes, int n_in,
                              void* d_out, int out_size) {
    const float* x       = (const float*)d_in[0];
    const float* e1_Wih  = (const float*)d_in[1];
    const float* e1_Whh  = (const float*)d_in[2];
    const float* e1_bih  = (const float*)d_in[3];
    const float* e1_bhh  = (const float*)d_in[4];
    const float* e2_Wih  = (const float*)d_in[5];
    const float* e2_Whh  = (const float*)d_in[6];
    const float* e2_bih  = (const float*)d_in[7];
    const float* e2_bhh  = (const float*)d_in[8];
    const float* e3_Wih  = (const float*)d_in[9];
    const float* e3_Whh  = (const float*)d_in[10];
    const float* e3_bih  = (const float*)d_in[11];
    const float* e3_bhh  = (const float*)d_in[12];
    const float* d1_Wih  = (const float*)d_in[13];
    const float* d1_Whh  = (const float*)d_in[14];
    const float* d1_bih  = (const float*)d_in[15];
    const float* d1_bhh  = (const float*)d_in[16];
    const float* d2_Wih  = (const float*)d_in[17];
    const float* d2_Whh  = (const float*)d_in[18];
    const float* d2_bih  = (const float*)d_in[19];
    const float* d2_bhh  = (const float*)d_in[20];
    const float* d3_Wih  = (const float*)d_in[21];
    const float* d3_Whh  = (const float*)d_in[22];
    const float* d3_bih  = (const float*)d_in[23];
    const float* d3_bhh  = (const float*)d_in[24];
    const float* out_W   = (const float*)d_in[25];
    const float* out_b   = (const float*)d_in[26];
    float* out = (float*)d_out;

    reset_flags_kernel<<<1, 384>>>();

    // --- encoder ---
    xg_e1_kernel<<<(T_SEQ * 2048) / 256, 256>>>(x, e1_Wih, e1_bih, e1_bhh);
    lstm_scan_kernel<512><<<32, 512>>>(e1_Whh, 0, 2048, 0, 0);          // ys -> A

    gemm_bias_kernel<<<dim3(1024 / 64, T_SEQ / 64), 256>>>(0, e2_Wih, e2_bih, e2_bhh, 1024, 512);
    lstm_scan_kernel<256><<<16, 512>>>(e2_Whh, 0, 1024, 1, 64);         // ys -> B

    gemm_bias_kernel<<<dim3(512 / 64, T_SEQ / 64), 256>>>(1, e3_Wih, e3_bih, e3_bhh, 512, 256);
    lstm_scan_kernel<128><<<8, 512>>>(e3_Whh, 0, 512, 0, 128);          // ys -> A (z = last row)

    // --- decoder ---
    gemv_d1_kernel<<<2, 256>>>(d1_Wih, d1_bih, d1_bhh);                 // constant xg row
    lstm_scan_kernel<128><<<8, 512>>>(d1_Whh, 1, 0, 1, 192);            // ys -> B

    gemm_bias_kernel<<<dim3(1024 / 64, T_SEQ / 64), 256>>>(1, d2_Wih, d2_bih, d2_bhh, 1024, 128);
    lstm_scan_kernel<256><<<16, 512>>>(d2_Whh, 0, 1024, 0, 256);        // ys -> A

    gemm_bias_kernel<<<dim3(2048 / 64, T_SEQ / 64), 256>>>(0, d3_Wih, d3_bih, d3_bhh, 2048, 256);
    lstm_scan_kernel<512><<<32, 512>>>(d3_Whh, 0, 2048, 1, 320);        // ys -> B

    out_proj_kernel<<<(T_SEQ * 32) / 256, 256>>>(out_W, out_b, out);
}

// round 2
// speedup vs baseline: 1.4782x; 1.4782x over previous
#include <cuda_runtime.h>
#include <cuda_bf16.h>
#include <cstdint>

// ---------------------------------------------------------------------------
// LSTM autoencoder: 6 LSTM layers (H = 512,256,128,128,256,512) over T=8192,
// final linear projection to 1 feature.
//
//   - xg = X @ Wih^T + (bih+bhh) precomputed per layer (tiled SGEMM).
//   - Serial recurrence: persistent multi-CTA scan. Recurrent weights live in
//     registers. Cross-CTA h exchange uses self-synchronizing 64-bit words
//     (epoch<<32 | float bits) -- one L2 round trip per step, no fences.
// ---------------------------------------------------------------------------

#define T_SEQ 8192

__device__ float g_xg [T_SEQ * 2048];            // xg buffer (max 4H = 2048)
__device__ float g_ysA[T_SEQ * 512];             // layer-output ping
__device__ float g_ysB[T_SEQ * 512];             // layer-output pong
__device__ float g_gvec[2048];                   // constant xg row for d1
__device__ unsigned long long g_hw[2][512];      // packed (epoch|h) words

// ---------------------------------------------------------------------------
__device__ __forceinline__ float sigmoid_f(float x) {
    return __fdividef(1.0f, 1.0f + __expf(-x));
}
__device__ __forceinline__ float tanh_f(float x) {
    x = fminf(fmaxf(x, -15.0f), 15.0f);
    float e = __expf(-2.0f * x);
    return __fdividef(1.0f - e, 1.0f + e);
}
__device__ __forceinline__ void fma2(unsigned long long& d,
                                     unsigned long long a,
                                     unsigned long long b) {
    asm("fma.rn.f32x2 %0, %1, %2, %0;" : "+l"(d) : "l"(a), "l"(b));
}
__device__ __forceinline__ float f32x2_sum(unsigned long long v) {
    return __uint_as_float((unsigned)v) + __uint_as_float((unsigned)(v >> 32));
}

// ---------------------------------------------------------------------------
// xg for layer e1 (in_dim = 1)
// ---------------------------------------------------------------------------
__global__ void xg_e1_kernel(const float* __restrict__ x,
                             const float* __restrict__ Wih,
                             const float* __restrict__ bih,
                             const float* __restrict__ bhh) {
    int idx = blockIdx.x * blockDim.x + threadIdx.x;
    int t = idx >> 11;
    int g = idx & 2047;
    g_xg[idx] = x[t] * Wih[g] + bih[g] + bhh[g];
}

// ---------------------------------------------------------------------------
// Tiled SGEMM: g_xg[M,N] = A[M,K] @ W[N,K]^T + (b1+b2)[N]   (M = 8192)
// ---------------------------------------------------------------------------
__global__ void __launch_bounds__(256) gemm_bias_kernel(
        int a_sel,
        const float* __restrict__ W,
        const float* __restrict__ b1,
        const float* __restrict__ b2,
        int N, int K) {
    const float* A = a_sel ? g_ysB : g_ysA;
    __shared__ float As[16][68];
    __shared__ float Ws[16][68];

    int tid = threadIdx.x;
    int bx = blockIdx.x;
    int by = blockIdx.y;
    int tx = tid & 15;
    int ty = tid >> 4;
    int lr = tid >> 2;
    int lc = (tid & 3) * 4;

    const float* Ag = A + (size_t)(by * 64 + lr) * K + lc;
    const float* Wg = W + (size_t)(bx * 64 + lr) * K + lc;

    float acc[4][4] = {};

    for (int k0 = 0; k0 < K; k0 += 16) {
        float4 av = *(const float4*)(Ag + k0);
        float4 wv = *(const float4*)(Wg + k0);
        As[lc + 0][lr] = av.x; As[lc + 1][lr] = av.y;
        As[lc + 2][lr] = av.z; As[lc + 3][lr] = av.w;
        Ws[lc + 0][lr] = wv.x; Ws[lc + 1][lr] = wv.y;
        Ws[lc + 2][lr] = wv.z; Ws[lc + 3][lr] = wv.w;
        __syncthreads();
#pragma unroll
        for (int k = 0; k < 16; ++k) {
            float a[4], w4[4];
#pragma unroll
            for (int i = 0; i < 4; ++i) a[i]  = As[k][ty * 4 + i];
#pragma unroll
            for (int j = 0; j < 4; ++j) w4[j] = Ws[k][tx * 4 + j];
#pragma unroll
            for (int i = 0; i < 4; ++i)
#pragma unroll
                for (int j = 0; j < 4; ++j)
                    acc[i][j] += a[i] * w4[j];
        }
        __syncthreads();
    }

    int n0 = bx * 64 + tx * 4;
    float bs[4];
#pragma unroll
    for (int j = 0; j < 4; ++j) bs[j] = b1[n0 + j] + b2[n0 + j];
#pragma unroll
    for (int i = 0; i < 4; ++i) {
        int m = by * 64 + ty * 4 + i;
        float4 o = make_float4(acc[i][0] + bs[0], acc[i][1] + bs[1],
                               acc[i][2] + bs[2], acc[i][3] + bs[3]);
        *(float4*)&g_xg[(size_t)m * N + n0] = o;
    }
}

// ---------------------------------------------------------------------------
// gvec for d1: gvec[n] = z @ Wih[n,:]^T + b1[n] + b2[n], z = last row of ysA.
// ---------------------------------------------------------------------------
__global__ void gemv_d1_kernel(const float* __restrict__ Wih,
                               const float* __restrict__ b1,
                               const float* __restrict__ b2) {
    int n = blockIdx.x * blockDim.x + threadIdx.x;
    if (n >= 512) return;
    const float* z = g_ysA + (size_t)(T_SEQ - 1) * 128;
    float s = b1[n] + b2[n];
    const float* w = Wih + (size_t)n * 128;
#pragma unroll
    for (int k = 0; k < 128; k += 4) {
        float4 zv = *(const float4*)(z + k);
        float4 wv = *(const float4*)(w + k);
        s += zv.x * wv.x + zv.y * wv.y + zv.z * wv.z + zv.w * wv.w;
    }
    g_gvec[n] = s;
}

// ---------------------------------------------------------------------------
// Persistent LSTM scan, v2.
//   Grid: B = H/8 CTAs, 512 threads. CTA owns U=8 units (32 rows of Whh).
//   Thread (kseg 0..15, row 0..31): KLEN = H/16 weights in regs (f32x2 pairs).
//   Warp 0      : matvec kseg0 + reduce + gates + publish (lanes 0..7 keep c).
//   Warps 1,2   : fetchers -- spin-read packed h words -> smem h_s.
//   Warps 3..15 : matvec only.
//   Sync per step: 2x __syncthreads; cross-CTA via (epoch|value) words in L2.
// ---------------------------------------------------------------------------
template <int H>
__global__ void __launch_bounds__(512, 1) lstm_scan2_kernel(
        const float* __restrict__ Whh,   // [4H, H]
        int xg_sel,                       // 0: g_xg, 1: g_gvec
        int xg_stride,                    // 4H or 0
        int ys_sel,                       // 0: g_ysA, 1: g_ysB
        unsigned ep_base) {               // layer epoch base (layer << 14)
    constexpr int KSEG = 16;
    constexpr int KLEN = H / 16;       // 32 / 16 / 8
    constexpr int NQ   = KLEN / 2;     // f32x2 pairs per thread
    constexpr int NW   = H / 64;       // words per fetch lane (2 fetch warps)

    const float* xgp = xg_sel ? g_gvec : g_xg;
    float* ys = ys_sel ? g_ysB : g_ysA;

    const int b    = blockIdx.x;
    const int tid  = threadIdx.x;
    const int wid  = tid >> 5;
    const int lane = tid & 31;
    const int kseg = wid;              // one kseg per warp
    const int row  = lane;             // 0..31
    const int gate = row >> 3;
    const int unit = row & 7;
    const int grow = gate * H + b * 8 + unit;   // global Whh / xg row

    // Load this thread's weight slice into registers (f32x2 packed).
    unsigned long long wq[NQ];
    {
        const unsigned long long* wp = (const unsigned long long*)
            (Whh + (size_t)grow * H + kseg * KLEN);
#pragma unroll
        for (int i = 0; i < NQ; ++i) wq[i] = wp[i];
    }

    __shared__ __align__(16) float h_s[H];
    __shared__ float red[KSEG][32];

    float c = 0.0f;          // cell state (lanes 0..7 of warp 0)
    float xval = 0.0f;

    // Publish initial h0 = 0 with epoch ep_base into parity-0 buffer.
    if (wid == 0 && row < 8) {
        *(volatile unsigned long long*)&g_hw[0][b * 8 + row] =
            ((unsigned long long)ep_base) << 32;   // value bits = 0.0f
    }

    for (int t = 0; t < T_SEQ; ++t) {
        if (wid == 0) {
            // prefetch xg[t][grow] (independent of h)
            xval = __ldg(xgp + (size_t)t * xg_stride + grow);
        } else if (wid <= 2) {
            // fetch h_t (epoch ep_base + t) into smem
            const unsigned ep = ep_base + (unsigned)t;
            const int base = ((wid - 1) * 32 + lane) * NW;
            const volatile unsigned long long* src = &g_hw[t & 1][base];
            unsigned long long v[NW];
            bool bad;
            do {
                bad = false;
#pragma unroll
                for (int i = 0; i < NW; ++i) v[i] = src[i];
#pragma unroll
                for (int i = 0; i < NW; ++i)
                    bad |= ((unsigned)(v[i] >> 32) != ep);
            } while (bad);
#pragma unroll
            for (int i = 0; i < NW; ++i)
                h_s[base + i] = __uint_as_float((unsigned)v[i]);
        }
        __syncthreads();

        // matvec partial over this thread's k-slice (f32x2 FMAs, 4 lanes)
        {
            const unsigned long long* hq =
                (const unsigned long long*)&h_s[kseg * KLEN];
            unsigned long long a0 = 0ull, a1 = 0ull;
#pragma unroll
            for (int i = 0; i < NQ; i += 2) {
                ulonglong2 hv = *(const ulonglong2*)(hq + i);
                fma2(a0, wq[i],     hv.x);
                fma2(a1, wq[i + 1], hv.y);
            }
            red[kseg][row] = f32x2_sum(a0) + f32x2_sum(a1);
        }
        __syncthreads();

        if (wid == 0) {
            // reduce 16 ksegs for this lane's row
            float s0 = xval, s1 = 0.0f, s2 = 0.0f, s3 = 0.0f;
#pragma unroll
            for (int k = 0; k < KSEG; k += 4) {
                s0 += red[k][lane];
                s1 += red[k + 1][lane];
                s2 += red[k + 2][lane];
                s3 += red[k + 3][lane];
            }
            float s = (s0 + s1) + (s2 + s3);

            // gather the 4 gate sums of this lane's unit
            float gi = __shfl_sync(0xffffffffu, s, unit);
            float gf = __shfl_sync(0xffffffffu, s, 8 + unit);
            float gg = __shfl_sync(0xffffffffu, s, 16 + unit);
            float go = __shfl_sync(0xffffffffu, s, 24 + unit);

            if (row < 8) {
                float i_ = sigmoid_f(gi);
                float f_ = sigmoid_f(gf);
                float g_ = tanh_f(gg);
                float o_ = sigmoid_f(go);
                c = f_ * c + i_ * g_;
                float h = o_ * tanh_f(c);
                unsigned long long word =
                    (((unsigned long long)(ep_base + (unsigned)t + 1u)) << 32)
                    | (unsigned long long)__float_as_uint(h);
                *(volatile unsigned long long*)&g_hw[(t + 1) & 1][b * 8 + row]
                    = word;
                ys[(size_t)t * H + b * 8 + row] = h;
            }
        }
    }
}

// ---------------------------------------------------------------------------
// Final projection: out[t] = ys_d3[t,:] . out_W + out_b
// ---------------------------------------------------------------------------
__global__ void out_proj_kernel(const float* __restrict__ w,
                                const float* __restrict__ bias,
                                float* __restrict__ out) {
    int gtid = blockIdx.x * blockDim.x + threadIdx.x;
    int warp = gtid >> 5;
    int lane = threadIdx.x & 31;
    if (warp >= T_SEQ) return;
    const float* y = g_ysB + (size_t)warp * 512;
    float s = 0.0f;
#pragma unroll
    for (int j = 0; j < 16; ++j) {
        s += y[lane + 32 * j] * w[lane + 32 * j];
    }
#pragma unroll
    for (int off = 16; off > 0; off >>= 1)
        s += __shfl_down_sync(0xffffffffu, s, off);
    if (lane == 0) out[warp] = s + bias[0];
}

// ---------------------------------------------------------------------------
extern "C" void kernel_launch(void* const* d_in, const int* in_sizes, int n_in,
                              void* d_out, int out_size) {
    const float* x       = (const float*)d_in[0];
    const float* e1_Wih  = (const float*)d_in[1];
    const float* e1_Whh  = (const float*)d_in[2];
    const float* e1_bih  = (const float*)d_in[3];
    const float* e1_bhh  = (const float*)d_in[4];
    const float* e2_Wih  = (const float*)d_in[5];
    const float* e2_Whh  = (const float*)d_in[6];
    const float* e2_bih  = (const float*)d_in[7];
    const float* e2_bhh  = (const float*)d_in[8];
    const float* e3_Wih  = (const float*)d_in[9];
    const float* e3_Whh  = (const float*)d_in[10];
    const float* e3_bih  = (const float*)d_in[11];
    const float* e3_bhh  = (const float*)d_in[12];
    const float* d1_Wih  = (const float*)d_in[13];
    const float* d1_Whh  = (const float*)d_in[14];
    const float* d1_bih  = (const float*)d_in[15];
    const float* d1_bhh  = (const float*)d_in[16];
    const float* d2_Wih  = (const float*)d_in[17];
    const float* d2_Whh  = (const float*)d_in[18];
    const float* d2_bih  = (const float*)d_in[19];
    const float* d2_bhh  = (const float*)d_in[20];
    const float* d3_Wih  = (const float*)d_in[21];
    const float* d3_Whh  = (const float*)d_in[22];
    const float* d3_bih  = (const float*)d_in[23];
    const float* d3_bhh  = (const float*)d_in[24];
    const float* out_W   = (const float*)d_in[25];
    const float* out_b   = (const float*)d_in[26];
    float* out = (float*)d_out;

    // --- encoder ---
    xg_e1_kernel<<<(T_SEQ * 2048) / 256, 256>>>(x, e1_Wih, e1_bih, e1_bhh);
    lstm_scan2_kernel<512><<<64, 512>>>(e1_Whh, 0, 2048, 0, 0u << 14);

    gemm_bias_kernel<<<dim3(1024 / 64, T_SEQ / 64), 256>>>(0, e2_Wih, e2_bih, e2_bhh, 1024, 512);
    lstm_scan2_kernel<256><<<32, 512>>>(e2_Whh, 0, 1024, 1, 1u << 14);

    gemm_bias_kernel<<<dim3(512 / 64, T_SEQ / 64), 256>>>(1, e3_Wih, e3_bih, e3_bhh, 512, 256);
    lstm_scan2_kernel<128><<<16, 512>>>(e3_Whh, 0, 512, 0, 2u << 14);

    // --- decoder ---
    gemv_d1_kernel<<<2, 256>>>(d1_Wih, d1_bih, d1_bhh);
    lstm_scan2_kernel<128><<<16, 512>>>(d1_Whh, 1, 0, 1, 3u << 14);

    gemm_bias_kernel<<<dim3(1024 / 64, T_SEQ / 64), 256>>>(1, d2_Wih, d2_bih, d2_bhh, 1024, 128);
    lstm_scan2_kernel<256><<<32, 512>>>(d2_Whh, 0, 1024, 0, 4u << 14);

    gemm_bias_kernel<<<dim3(2048 / 64, T_SEQ / 64), 256>>>(0, d3_Wih, d3_bih, d3_bhh, 2048, 256);
    lstm_scan2_kernel<512><<<64, 512>>>(d3_Whh, 0, 2048, 1, 5u << 14);

    out_proj_kernel<<<(T_SEQ * 32) / 256, 256>>>(out_W, out_b, out);
}

// round 4
// speedup vs baseline: 2.0212x; 1.3674x over previous
#include <cuda_runtime.h>
#include <cuda_bf16.h>
#include <cstdint>

// ---------------------------------------------------------------------------
// LSTM autoencoder: 6 LSTM layers (H = 512,256,128,128,256,512) over T=8192,
// final linear projection to 1 feature.
//
//   - xg = X @ Wih^T + (bih+bhh) precomputed per layer (tiled SGEMM).
//   - Serial recurrence: persistent multi-CTA scan. Recurrent weights live in
//     registers. Cross-CTA h exchange uses self-synchronizing 64-bit words
//     (epoch<<32 | float bits); every matvec warp polls its own slice.
//   - Two __syncthreads per step (proven-safe v2 skeleton): sync_A gates red
//     reuse, sync_B publishes red to warp 0. Polls of step t+1 overlap
//     warp 0's step-t reduce/gates/publish tail.
// ---------------------------------------------------------------------------

#define T_SEQ 8192

__device__ float g_xg [T_SEQ * 2048];            // xg buffer (max 4H = 2048)
__device__ float g_ysA[T_SEQ * 512];             // layer-output ping
__device__ float g_ysB[T_SEQ * 512];             // layer-output pong
__device__ float g_gvec[2048];                   // constant xg row for d1
__device__ unsigned long long g_hw[2][512];      // packed (epoch|h) words

// ---------------------------------------------------------------------------
__device__ __forceinline__ float sigmoid_f(float x) {
    return __fdividef(1.0f, 1.0f + __expf(-x));
}
__device__ __forceinline__ float tanh_f(float x) {
    x = fminf(fmaxf(x, -15.0f), 15.0f);
    float e = __expf(-2.0f * x);
    return __fdividef(1.0f - e, 1.0f + e);
}
__device__ __forceinline__ void fma2(unsigned long long& d,
                                     unsigned long long a,
                                     unsigned long long b) {
    asm("fma.rn.f32x2 %0, %1, %2, %0;" : "+l"(d) : "l"(a), "l"(b));
}
__device__ __forceinline__ float f32x2_sum(unsigned long long v) {
    return __uint_as_float((unsigned)v) + __uint_as_float((unsigned)(v >> 32));
}

// ---------------------------------------------------------------------------
// xg for layer e1 (in_dim = 1)
// ---------------------------------------------------------------------------
__global__ void xg_e1_kernel(const float* __restrict__ x,
                             const float* __restrict__ Wih,
                             const float* __restrict__ bih,
                             const float* __restrict__ bhh) {
    int idx = blockIdx.x * blockDim.x + threadIdx.x;
    int t = idx >> 11;
    int g = idx & 2047;
    g_xg[idx] = x[t] * Wih[g] + bih[g] + bhh[g];
}

// ---------------------------------------------------------------------------
// Tiled SGEMM: g_xg[M,N] = A[M,K] @ W[N,K]^T + (b1+b2)[N]   (M = 8192)
// ---------------------------------------------------------------------------
__global__ void __launch_bounds__(256) gemm_bias_kernel(
        int a_sel,
        const float* __restrict__ W,
        const float* __restrict__ b1,
        const float* __restrict__ b2,
        int N, int K) {
    const float* A = a_sel ? g_ysB : g_ysA;
    __shared__ float As[16][68];
    __shared__ float Ws[16][68];

    int tid = threadIdx.x;
    int bx = blockIdx.x;
    int by = blockIdx.y;
    int tx = tid & 15;
    int ty = tid >> 4;
    int lr = tid >> 2;
    int lc = (tid & 3) * 4;

    const float* Ag = A + (size_t)(by * 64 + lr) * K + lc;
    const float* Wg = W + (size_t)(bx * 64 + lr) * K + lc;

    float acc[4][4] = {};

    for (int k0 = 0; k0 < K; k0 += 16) {
        float4 av = *(const float4*)(Ag + k0);
        float4 wv = *(const float4*)(Wg + k0);
        As[lc + 0][lr] = av.x; As[lc + 1][lr] = av.y;
        As[lc + 2][lr] = av.z; As[lc + 3][lr] = av.w;
        Ws[lc + 0][lr] = wv.x; Ws[lc + 1][lr] = wv.y;
        Ws[lc + 2][lr] = wv.z; Ws[lc + 3][lr] = wv.w;
        __syncthreads();
#pragma unroll
        for (int k = 0; k < 16; ++k) {
            float a[4], w4[4];
#pragma unroll
            for (int i = 0; i < 4; ++i) a[i]  = As[k][ty * 4 + i];
#pragma unroll
            for (int j = 0; j < 4; ++j) w4[j] = Ws[k][tx * 4 + j];
#pragma unroll
            for (int i = 0; i < 4; ++i)
#pragma unroll
                for (int j = 0; j < 4; ++j)
                    acc[i][j] += a[i] * w4[j];
        }
        __syncthreads();
    }

    int n0 = bx * 64 + tx * 4;
    float bs[4];
#pragma unroll
    for (int j = 0; j < 4; ++j) bs[j] = b1[n0 + j] + b2[n0 + j];
#pragma unroll
    for (int i = 0; i < 4; ++i) {
        int m = by * 64 + ty * 4 + i;
        float4 o = make_float4(acc[i][0] + bs[0], acc[i][1] + bs[1],
                               acc[i][2] + bs[2], acc[i][3] + bs[3]);
        *(float4*)&g_xg[(size_t)m * N + n0] = o;
    }
}

// ---------------------------------------------------------------------------
// gvec for d1: gvec[n] = z @ Wih[n,:]^T + b1[n] + b2[n], z = last row of ysA.
// ---------------------------------------------------------------------------
__global__ void gemv_d1_kernel(const float* __restrict__ Wih,
                               const float* __restrict__ b1,
                               const float* __restrict__ b2) {
    int n = blockIdx.x * blockDim.x + threadIdx.x;
    if (n >= 512) return;
    const float* z = g_ysA + (size_t)(T_SEQ - 1) * 128;
    float s = b1[n] + b2[n];
    const float* w = Wih + (size_t)n * 128;
#pragma unroll
    for (int k = 0; k < 128; k += 4) {
        float4 zv = *(const float4*)(z + k);
        float4 wv = *(const float4*)(w + k);
        s += zv.x * wv.x + zv.y * wv.y + zv.z * wv.z + zv.w * wv.w;
    }
    g_gvec[n] = s;
}

// ---------------------------------------------------------------------------
// Persistent LSTM scan, v4.
//   Grid: B = H/8 CTAs, 512 threads. CTA owns U=8 units (32 rows of Whh).
//   Warp w of 16 = kseg w: lanes < KLEN poll their own packed h word
//   (volatile), stage into this warp's smem strip.
//   Loop skeleton (v2-proven):  poll -> sync_A -> matvec/red -> sync_B ->
//   warp0 reduce+gates+publish (overlapped with other warps' next-step polls).
// ---------------------------------------------------------------------------
template <int H>
__global__ void __launch_bounds__(512, 1) lstm_scan4_kernel(
        const float* __restrict__ Whh,   // [4H, H]
        int xg_sel,                       // 0: g_xg, 1: g_gvec
        int xg_stride,                    // 4H or 0
        int ys_sel,                       // 0: g_ysA, 1: g_ysB
        unsigned ep_base) {               // layer epoch base (layer << 14)
    constexpr int KSEG = 16;
    constexpr int KLEN = H / KSEG;     // 32 / 16 / 8
    constexpr int NQ   = KLEN / 2;     // f32x2 pairs per thread

    const float* xgp = xg_sel ? g_gvec : g_xg;
    float* ys = ys_sel ? g_ysB : g_ysA;

    const int b    = blockIdx.x;
    const int tid  = threadIdx.x;
    const int wid  = tid >> 5;         // kseg
    const int lane = tid & 31;
    const int gate = lane >> 3;
    const int unit = lane & 7;
    const int grow = gate * H + b * 8 + unit;   // global Whh / xg row
    const int hbase = wid * KLEN;               // this warp's h slice

    // Load this thread's weight slice into registers (f32x2 packed).
    unsigned long long wq[NQ];
    {
        const unsigned long long* wp = (const unsigned long long*)
            (Whh + (size_t)grow * H + hbase);
#pragma unroll
        for (int i = 0; i < NQ; ++i) wq[i] = wp[i];
    }

    __shared__ __align__(16) float h_s[H];
    __shared__ float red[KSEG][32];

    float c = 0.0f;          // cell state (lanes 0..7 of warp 0)
    float xval = 0.0f;

    // Publish initial h0 = 0 with epoch ep_base into parity-0 buffer.
    if (wid == 0 && lane < 8) {
        *(volatile unsigned long long*)&g_hw[0][b * 8 + lane] =
            ((unsigned long long)ep_base) << 32;   // value bits = 0.0f
    }

    for (int t = 0; t < T_SEQ; ++t) {
        if (wid == 0) {
            // prefetch xg[t][grow] (independent of h)
            xval = __ldg(xgp + (size_t)t * xg_stride + grow);
        }

        // Poll own h word (one per lane), stage into this warp's smem strip.
        if (lane < KLEN) {
            const unsigned ep = ep_base + (unsigned)t;
            const volatile unsigned long long* src =
                &g_hw[t & 1][hbase + lane];
            unsigned long long v;
            do { v = *src; } while ((unsigned)(v >> 32) != ep);
            h_s[hbase + lane] = __uint_as_float((unsigned)v);
        }
        __syncthreads();   // sync_A: h_s staged; warp0's previous reduce done

        // matvec partial over this warp's k-slice (f32x2 FMAs, 2 chains)
        {
            const unsigned long long* hq =
                (const unsigned long long*)&h_s[hbase];
            unsigned long long a0 = 0ull, a1 = 0ull;
#pragma unroll
            for (int i = 0; i < NQ; i += 2) {
                fma2(a0, wq[i],     hq[i]);
                if (i + 1 < NQ) fma2(a1, wq[i + 1], hq[i + 1]);
            }
            red[wid][lane] = f32x2_sum(a0) + f32x2_sum(a1);
        }
        __syncthreads();   // sync_B: red complete

        if (wid == 0) {
            // reduce 16 ksegs for this lane's row
            float s0 = xval, s1 = 0.0f, s2 = 0.0f, s3 = 0.0f;
#pragma unroll
            for (int k = 0; k < KSEG; k += 4) {
                s0 += red[k][lane];
                s1 += red[k + 1][lane];
                s2 += red[k + 2][lane];
                s3 += red[k + 3][lane];
            }
            float s = (s0 + s1) + (s2 + s3);

            // activation for this lane's row: tanh for gate 2, sigmoid else,
            // via shared chain  tanh(x) = 2*sigmoid(2x) - 1.
            bool isg = (gate == 2);
            float sa = isg ? 2.0f * s : s;
            float sg = sigmoid_f(sa);
            float act = isg ? 2.0f * sg - 1.0f : sg;

            // gather activated gate values of this lane's unit
            float i_ = __shfl_sync(0xffffffffu, act, unit);
            float f_ = __shfl_sync(0xffffffffu, act, 8 + unit);
            float g_ = __shfl_sync(0xffffffffu, act, 16 + unit);
            float o_ = __shfl_sync(0xffffffffu, act, 24 + unit);

            if (lane < 8) {
                c = f_ * c + i_ * g_;
                float h = o_ * tanh_f(c);
                unsigned long long word =
                    (((unsigned long long)(ep_base + (unsigned)t + 1u)) << 32)
                    | (unsigned long long)__float_as_uint(h);
                *(volatile unsigned long long*)&g_hw[(t + 1) & 1][b * 8 + lane]
                    = word;
                ys[(size_t)t * H + b * 8 + lane] = h;
            }
        }
        // other warps run ahead into next-step poll while warp 0 finishes.
    }
}

// ---------------------------------------------------------------------------
// Final projection: out[t] = ys_d3[t,:] . out_W + out_b
// ---------------------------------------------------------------------------
__global__ void out_proj_kernel(const float* __restrict__ w,
                                const float* __restrict__ bias,
                                float* __restrict__ out) {
    int gtid = blockIdx.x * blockDim.x + threadIdx.x;
    int warp = gtid >> 5;
    int lane = threadIdx.x & 31;
    if (warp >= T_SEQ) return;
    const float* y = g_ysB + (size_t)warp * 512;
    float s = 0.0f;
#pragma unroll
    for (int j = 0; j < 16; ++j) {
        s += y[lane + 32 * j] * w[lane + 32 * j];
    }
#pragma unroll
    for (int off = 16; off > 0; off >>= 1)
        s += __shfl_down_sync(0xffffffffu, s, off);
    if (lane == 0) out[warp] = s + bias[0];
}

// ---------------------------------------------------------------------------
extern "C" void kernel_launch(void* const* d_in, const int* in_sizes, int n_in,
                              void* d_out, int out_size) {
    const float* x       = (const float*)d_in[0];
    const float* e1_Wih  = (const float*)d_in[1];
    const float* e1_Whh  = (const float*)d_in[2];
    const float* e1_bih  = (const float*)d_in[3];
    const float* e1_bhh  = (const float*)d_in[4];
    const float* e2_Wih  = (const float*)d_in[5];
    const float* e2_Whh  = (const float*)d_in[6];
    const float* e2_bih  = (const float*)d_in[7];
    const float* e2_bhh  = (const float*)d_in[8];
    const float* e3_Wih  = (const float*)d_in[9];
    const float* e3_Whh  = (const float*)d_in[10];
    const float* e3_bih  = (const float*)d_in[11];
    const float* e3_bhh  = (const float*)d_in[12];
    const float* d1_Wih  = (const float*)d_in[13];
    const float* d1_Whh  = (const float*)d_in[14];
    const float* d1_bih  = (const float*)d_in[15];
    const float* d1_bhh  = (const float*)d_in[16];
    const float* d2_Wih  = (const float*)d_in[17];
    const float* d2_Whh  = (const float*)d_in[18];
    const float* d2_bih  = (const float*)d_in[19];
    const float* d2_bhh  = (const float*)d_in[20];
    const float* d3_Wih  = (const float*)d_in[21];
    const float* d3_Whh  = (const float*)d_in[22];
    const float* d3_bih  = (const float*)d_in[23];
    const float* d3_bhh  = (const float*)d_in[24];
    const float* out_W   = (const float*)d_in[25];
    const float* out_b   = (const float*)d_in[26];
    float* out = (float*)d_out;

    // --- encoder ---
    xg_e1_kernel<<<(T_SEQ * 2048) / 256, 256>>>(x, e1_Wih, e1_bih, e1_bhh);
    lstm_scan4_kernel<512><<<64, 512>>>(e1_Whh, 0, 2048, 0, 0u << 14);

    gemm_bias_kernel<<<dim3(1024 / 64, T_SEQ / 64), 256>>>(0, e2_Wih, e2_bih, e2_bhh, 1024, 512);
    lstm_scan4_kernel<256><<<32, 512>>>(e2_Whh, 0, 1024, 1, 1u << 14);

    gemm_bias_kernel<<<dim3(512 / 64, T_SEQ / 64), 256>>>(1, e3_Wih, e3_bih, e3_bhh, 512, 256);
    lstm_scan4_kernel<128><<<16, 512>>>(e3_Whh, 0, 512, 0, 2u << 14);

    // --- decoder ---
    gemv_d1_kernel<<<2, 256>>>(d1_Wih, d1_bih, d1_bhh);
    lstm_scan4_kernel<128><<<16, 512>>>(d1_Whh, 1, 0, 1, 3u << 14);

    gemm_bias_kernel<<<dim3(1024 / 64, T_SEQ / 64), 256>>>(1, d2_Wih, d2_bih, d2_bhh, 1024, 128);
    lstm_scan4_kernel<256><<<32, 512>>>(d2_Whh, 0, 1024, 0, 4u << 14);

    gemm_bias_kernel<<<dim3(2048 / 64, T_SEQ / 64), 256>>>(0, d3_Wih, d3_bih, d3_bhh, 2048, 256);
    lstm_scan4_kernel<512><<<64, 512>>>(d3_Whh, 0, 2048, 1, 5u << 14);

    out_proj_kernel<<<(T_SEQ * 32) / 256, 256>>>(out_W, out_b, out);
}

// round 5
// speedup vs baseline: 4.4388x; 2.1961x over previous
#include <cuda_runtime.h>
#include <cuda_bf16.h>
#include <cstdint>

// ---------------------------------------------------------------------------
// LSTM autoencoder, pipelined: encoder layers e1/e2/e3 run CONCURRENTLY in one
// 112-CTA kernel (skewed systolically by 1 step); same for decoder d1/d2/d3.
// Gates = [Whh | Wih] . [h_own ; y_producer] + bias, computed per step.
// Cross-CTA / cross-layer exchange: per-layer 8-deep rings of packed
// (epoch<<32 | float) words + per-layer progress counters for back-pressure.
// ---------------------------------------------------------------------------

#define T_SEQ 8192
typedef unsigned long long ull;

__device__ float g_xg [T_SEQ * 2048];        // e1 input contribution
__device__ float g_ys [T_SEQ * 512];         // d3 output rows
__device__ float g_gvec[512];                // d1 constant input row
__device__ ull   g_ring[6][8][512];          // per-layer h rings
__device__ int   g_prog[6];                  // per-layer progress counters

// ---------------------------------------------------------------------------
__device__ __forceinline__ float sigmoid_f(float x) {
    return __fdividef(1.0f, 1.0f + __expf(-x));
}
__device__ __forceinline__ float tanh_f(float x) {
    x = fminf(fmaxf(x, -15.0f), 15.0f);
    float e = __expf(-2.0f * x);
    return __fdividef(1.0f - e, 1.0f + e);
}
__device__ __forceinline__ void fma2(ull& d, ull a, ull b) {
    asm("fma.rn.f32x2 %0, %1, %2, %0;" : "+l"(d) : "l"(a), "l"(b));
}
__device__ __forceinline__ float f32x2_sum(ull v) {
    return __uint_as_float((unsigned)v) + __uint_as_float((unsigned)(v >> 32));
}

// ---------------------------------------------------------------------------
__global__ void reset_prog_kernel() {
    if (threadIdx.x < 6) g_prog[threadIdx.x] = 0;
}

// xg for e1 (in_dim = 1): xg[t][g] = x[t]*Wih[g] + bih[g] + bhh[g]
__global__ void xg_e1_kernel(const float* __restrict__ x,
                             const float* __restrict__ Wih,
                             const float* __restrict__ bih,
                             const float* __restrict__ bhh) {
    int idx = blockIdx.x * blockDim.x + threadIdx.x;
    int t = idx >> 11;
    int g = idx & 2047;
    g_xg[idx] = x[t] * Wih[g] + bih[g] + bhh[g];
}

// gvec for d1: z = e3 final h (ring 2, slot 8192&7 = 0, words 0..127)
__global__ void gemv_d1_kernel(const float* __restrict__ Wih,
                               const float* __restrict__ b1,
                               const float* __restrict__ b2) {
    int n = blockIdx.x * blockDim.x + threadIdx.x;
    if (n >= 512) return;
    float s = b1[n] + b2[n];
    const float* w = Wih + (size_t)n * 128;
#pragma unroll 4
    for (int k = 0; k < 128; ++k) {
        float z = __uint_as_float((unsigned)g_ring[2][0][k]);
        s += z * w[k];
    }
    g_gvec[n] = s;
}

// ---------------------------------------------------------------------------
// One LSTM layer step-loop, run by B = H/8 CTAs inside a fused kernel.
//   XGMODE 0: input via Wih matvec (bias const)   [warps NWH..15 poll producer]
//   XGMODE 1: xg from g_xg row t (stride 2048)    [e1]
//   XGMODE 2: constant input row g_gvec           [d1]
// Epochs: h computed at step t is published with epoch t+1 in slot (t+1)&7.
// Own-h poll at step t: epoch t, slot t&7. Producer y_t: epoch t+1, slot (t+1)&7.
// Back-pressure: before finishing step t, wait g_prog[CONS] >= t-5 (ring 8).
// ---------------------------------------------------------------------------
template <int H, int HIN, int NWH, int XGMODE, int OWN, int PROD, int CONS,
          bool WRITE_YS>
__device__ __forceinline__ void run_layer(
        int b,
        const float* __restrict__ Whh,
        const float* __restrict__ Wih,
        const float* __restrict__ bih,
        const float* __restrict__ bhh) {
    constexpr int NWI  = 16 - NWH;
    constexpr int SL_H = H / NWH;
    constexpr int SL_I = (HIN > 0) ? (HIN / (NWI > 0 ? NWI : 1)) : 2;
    constexpr int NQH  = SL_H / 2;
    constexpr int NQI  = (HIN > 0) ? SL_I / 2 : 0;
    constexpr int NQMAX = (NQI > NQH) ? NQI : NQH;

    const int tid  = threadIdx.x;
    const int wid  = tid >> 5;
    const int lane = tid & 31;
    const int gate = lane >> 3;
    const int unit = lane & 7;
    const int grow = gate * H + b * 8 + unit;
    const bool is_h = (wid < NWH);

    // weights in registers (f32x2 packed)
    ull wq[NQMAX];
    if (is_h) {
        const ull* wp = (const ull*)(Whh + (size_t)grow * H + wid * SL_H);
#pragma unroll
        for (int i = 0; i < NQH; ++i) wq[i] = wp[i];
    } else {
        if constexpr (HIN > 0) {
            const ull* wp = (const ull*)
                (Wih + (size_t)grow * HIN + (wid - NWH) * SL_I);
#pragma unroll
            for (int i = 0; i < NQI; ++i) wq[i] = wp[i];
        }
    }

    __shared__ __align__(16) float h_s[H + ((HIN > 0) ? HIN : 0)];
    __shared__ float red[16][32];

    float c = 0.0f;
    float xconst = 0.0f;
    if (wid == 0) {
        if constexpr (XGMODE == 0) xconst = bih[grow] + bhh[grow];
        if constexpr (XGMODE == 2) xconst = g_gvec[grow];
    }

    // publish h0 = 0 with epoch 0 into slot 0
    if (wid == 0 && lane < 8) {
        *(volatile ull*)&g_ring[OWN][0][b * 8 + lane] = 0ull;
    }

    for (int t = 0; t < T_SEQ; ++t) {
        float xval = xconst;
        if (wid == 0) {
            if constexpr (XGMODE == 1)
                xval = __ldg(g_xg + (size_t)t * 2048 + grow);
        }

        // back-pressure on consumer layer progress (ring depth 8)
        if constexpr (CONS >= 0) {
            if (wid == 15 && lane == 31) {
                volatile int* pp = &g_prog[CONS];
                while (*pp < t - 5) { }
            }
        }

        // poll + stage this warp's slice
        if (is_h) {
            const volatile ull* src = &g_ring[OWN][t & 7][wid * SL_H];
#pragma unroll
            for (int j = 0; j < SL_H; j += 32) {
                int idx = j + lane;
                if (idx < SL_H) {
                    ull v;
                    do { v = src[idx]; } while ((unsigned)(v >> 32) != (unsigned)t);
                    h_s[wid * SL_H + idx] = __uint_as_float((unsigned)v);
                }
            }
        } else {
            if constexpr (HIN > 0) {
                const volatile ull* src =
                    &g_ring[PROD][(t + 1) & 7][(wid - NWH) * SL_I];
#pragma unroll
                for (int j = 0; j < SL_I; j += 32) {
                    int idx = j + lane;
                    if (idx < SL_I) {
                        ull v;
                        do { v = src[idx]; }
                        while ((unsigned)(v >> 32) != (unsigned)(t + 1));
                        h_s[H + (wid - NWH) * SL_I + idx] =
                            __uint_as_float((unsigned)v);
                    }
                }
            }
        }
        __syncthreads();   // sync_A

        // matvec partial over this warp's slice
        float part = 0.0f;
        if (is_h) {
            const ull* hq = (const ull*)&h_s[wid * SL_H];
            ull a0 = 0ull, a1 = 0ull;
#pragma unroll
            for (int i = 0; i < NQH; i += 2) {
                fma2(a0, wq[i], hq[i]);
                if (i + 1 < NQH) fma2(a1, wq[i + 1], hq[i + 1]);
            }
            part = f32x2_sum(a0) + f32x2_sum(a1);
        } else {
            if constexpr (HIN > 0) {
                const ull* hq = (const ull*)&h_s[H + (wid - NWH) * SL_I];
                ull a0 = 0ull, a1 = 0ull;
#pragma unroll
                for (int i = 0; i < NQI; i += 2) {
                    fma2(a0, wq[i], hq[i]);
                    if (i + 1 < NQI) fma2(a1, wq[i + 1], hq[i + 1]);
                }
                part = f32x2_sum(a0) + f32x2_sum(a1);
            }
        }
        red[wid][lane] = part;
        __syncthreads();   // sync_B

        if (wid == 0) {
            float s0 = xval, s1 = 0.0f, s2 = 0.0f, s3 = 0.0f;
#pragma unroll
            for (int k = 0; k < 16; k += 4) {
                s0 += red[k][lane];
                s1 += red[k + 1][lane];
                s2 += red[k + 2][lane];
                s3 += red[k + 3][lane];
            }
            float s = (s0 + s1) + (s2 + s3);

            // tanh for gate 2 via shared sigmoid chain
            bool isg = (gate == 2);
            float sa = isg ? 2.0f * s : s;
            float sg = sigmoid_f(sa);
            float act = isg ? 2.0f * sg - 1.0f : sg;

            float i_ = __shfl_sync(0xffffffffu, act, unit);
            float f_ = __shfl_sync(0xffffffffu, act, 8 + unit);
            float g_ = __shfl_sync(0xffffffffu, act, 16 + unit);
            float o_ = __shfl_sync(0xffffffffu, act, 24 + unit);

            if (lane < 8) {
                c = f_ * c + i_ * g_;
                float h = o_ * tanh_f(c);
                ull word = (((ull)(unsigned)(t + 1)) << 32)
                         | (ull)__float_as_uint(h);
                *(volatile ull*)&g_ring[OWN][(t + 1) & 7][b * 8 + lane] = word;
                if (WRITE_YS)
                    g_ys[(size_t)t * 512 + b * 8 + lane] = h;
            }
            if (b == 0 && lane == 8) {
                *(volatile int*)&g_prog[OWN] = t + 1;
            }
        }
        // non-warp-0 warps run ahead into the next step's poll.
    }
}

// ---------------------------------------------------------------------------
// Fused encoder: e1 (64 CTAs), e2 (32), e3 (16) -- 112 CTAs, single wave.
// ---------------------------------------------------------------------------
__global__ void __launch_bounds__(512, 1) encoder_kernel(
        const float* __restrict__ e1_Whh,
        const float* __restrict__ e2_Whh, const float* __restrict__ e2_Wih,
        const float* __restrict__ e2_bih, const float* __restrict__ e2_bhh,
        const float* __restrict__ e3_Whh, const float* __restrict__ e3_Wih,
        const float* __restrict__ e3_bih, const float* __restrict__ e3_bhh) {
    int bx = blockIdx.x;
    if (bx < 64) {
        run_layer<512, 0, 16, /*XG*/1, /*OWN*/0, /*PROD*/0, /*CONS*/1, false>(
            bx, e1_Whh, nullptr, nullptr, nullptr);
    } else if (bx < 96) {
        run_layer<256, 512, 8, 0, 1, 0, 2, false>(
            bx - 64, e2_Whh, e2_Wih, e2_bih, e2_bhh);
    } else {
        run_layer<128, 256, 8, 0, 2, 1, -1, false>(
            bx - 96, e3_Whh, e3_Wih, e3_bih, e3_bhh);
    }
}

// ---------------------------------------------------------------------------
// Fused decoder: d1 (16 CTAs), d2 (32), d3 (64) -- 112 CTAs, single wave.
// ---------------------------------------------------------------------------
__global__ void __launch_bounds__(512, 1) decoder_kernel(
        const float* __restrict__ d1_Whh,
        const float* __restrict__ d2_Whh, const float* __restrict__ d2_Wih,
        const float* __restrict__ d2_bih, const float* __restrict__ d2_bhh,
        const float* __restrict__ d3_Whh, const float* __restrict__ d3_Wih,
        const float* __restrict__ d3_bih, const float* __restrict__ d3_bhh) {
    int bx = blockIdx.x;
    if (bx < 16) {
        run_layer<128, 0, 16, /*XG*/2, /*OWN*/3, /*PROD*/3, /*CONS*/4, false>(
            bx, d1_Whh, nullptr, nullptr, nullptr);
    } else if (bx < 48) {
        run_layer<256, 128, 8, 0, 4, 3, 5, false>(
            bx - 16, d2_Whh, d2_Wih, d2_bih, d2_bhh);
    } else {
        run_layer<512, 256, 8, 0, 5, 4, -1, true>(
            bx - 48, d3_Whh, d3_Wih, d3_bih, d3_bhh);
    }
}

// ---------------------------------------------------------------------------
// Final projection: out[t] = ys_d3[t,:] . out_W + out_b
// ---------------------------------------------------------------------------
__global__ void out_proj_kernel(const float* __restrict__ w,
                                const float* __restrict__ bias,
                                float* __restrict__ out) {
    int gtid = blockIdx.x * blockDim.x + threadIdx.x;
    int warp = gtid >> 5;
    int lane = threadIdx.x & 31;
    if (warp >= T_SEQ) return;
    const float* y = g_ys + (size_t)warp * 512;
    float s = 0.0f;
#pragma unroll
    for (int j = 0; j < 16; ++j) {
        s += y[lane + 32 * j] * w[lane + 32 * j];
    }
#pragma unroll
    for (int off = 16; off > 0; off >>= 1)
        s += __shfl_down_sync(0xffffffffu, s, off);
    if (lane == 0) out[warp] = s + bias[0];
}

// ---------------------------------------------------------------------------
extern "C" void kernel_launch(void* const* d_in, const int* in_sizes, int n_in,
                              void* d_out, int out_size) {
    const float* x       = (const float*)d_in[0];
    const float* e1_Wih  = (const float*)d_in[1];
    const float* e1_Whh  = (const float*)d_in[2];
    const float* e1_bih  = (const float*)d_in[3];
    const float* e1_bhh  = (const float*)d_in[4];
    const float* e2_Wih  = (const float*)d_in[5];
    const float* e2_Whh  = (const float*)d_in[6];
    const float* e2_bih  = (const float*)d_in[7];
    const float* e2_bhh  = (const float*)d_in[8];
    const float* e3_Wih  = (const float*)d_in[9];
    const float* e3_Whh  = (const float*)d_in[10];
    const float* e3_bih  = (const float*)d_in[11];
    const float* e3_bhh  = (const float*)d_in[12];
    const float* d1_Wih  = (const float*)d_in[13];
    const float* d1_Whh  = (const float*)d_in[14];
    const float* d1_bih  = (const float*)d_in[15];
    const float* d1_bhh  = (const float*)d_in[16];
    const float* d2_Wih  = (const float*)d_in[17];
    const float* d2_Whh  = (const float*)d_in[18];
    const float* d2_bih  = (const float*)d_in[19];
    const float* d2_bhh  = (const float*)d_in[20];
    const float* d3_Wih  = (const float*)d_in[21];
    const float* d3_Whh  = (const float*)d_in[22];
    const float* d3_bih  = (const float*)d_in[23];
    const float* d3_bhh  = (const float*)d_in[24];
    const float* out_W   = (const float*)d_in[25];
    const float* out_b   = (const float*)d_in[26];
    float* out = (float*)d_out;

    reset_prog_kernel<<<1, 32>>>();
    xg_e1_kernel<<<(T_SEQ * 2048) / 256, 256>>>(x, e1_Wih, e1_bih, e1_bhh);

    encoder_kernel<<<112, 512>>>(e1_Whh,
                                 e2_Whh, e2_Wih, e2_bih, e2_bhh,
                                 e3_Whh, e3_Wih, e3_bih, e3_bhh);

    gemv_d1_kernel<<<2, 256>>>(d1_Wih, d1_bih, d1_bhh);

    decoder_kernel<<<112, 512>>>(d1_Whh,
                                 d2_Whh, d2_Wih, d2_bih, d2_bhh,
                                 d3_Whh, d3_Wih, d3_bih, d3_bhh);

    out_proj_kernel<<<(T_SEQ * 32) / 256, 256>>>(out_W, out_b, out);
}

// round 6
// speedup vs baseline: 4.6949x; 1.0577x over previous
#include <cuda_runtime.h>
#include <cuda_bf16.h>
#include <cstdint>

// ---------------------------------------------------------------------------
// LSTM autoencoder, pipelined: encoder layers e1/e2/e3 run CONCURRENTLY in one
// 112-CTA kernel (skewed systolically by 1 step); same for decoder d1/d2/d3.
// Gates = [Whh | Wih] . [h_own ; y_producer] + bias, computed per step.
// Cross-CTA / cross-layer exchange: per-layer 8-deep rings of packed
// (epoch<<32 | float) words + per-layer progress counters for back-pressure.
// e1 input folded to a scalar FMA; d1 input folded to a prologue dot.
// ---------------------------------------------------------------------------

#define T_SEQ 8192
typedef unsigned long long ull;

__device__ float g_ys [T_SEQ * 512];         // d3 output rows
__device__ ull   g_ring[6][8][512];          // per-layer h rings
__device__ int   g_prog[6];                  // per-layer progress counters

// ---------------------------------------------------------------------------
__device__ __forceinline__ float tanh_a(float x) {
    float y;
    asm("tanh.approx.f32 %0, %1;" : "=f"(y) : "f"(x));
    return y;
}
__device__ __forceinline__ void fma2(ull& d, ull a, ull b) {
    asm("fma.rn.f32x2 %0, %1, %2, %0;" : "+l"(d) : "l"(a), "l"(b));
}
__device__ __forceinline__ float f32x2_sum(ull v) {
    return __uint_as_float((unsigned)v) + __uint_as_float((unsigned)(v >> 32));
}

// ---------------------------------------------------------------------------
__global__ void reset_prog_kernel() {
    if (threadIdx.x < 6) g_prog[threadIdx.x] = 0;
}

// ---------------------------------------------------------------------------
// One LSTM layer step-loop, run by B = H/8 CTAs inside a fused kernel.
//   XGMODE 0: input via Wih matvec (bias const)  [warps NWH..15 poll producer]
//   XGMODE 1: scalar input x[t]: xval = x[t]*Wih[grow] + bias      [e1]
//   XGMODE 2: constant input row, prologue dot vs ring ZRING slot0 [d1]
// Epochs: h of step t published with epoch t+1 in slot (t+1)&7.
// Own-h poll at step t: epoch t, slot t&7. Producer y_t: epoch t+1, slot (t+1)&7.
// Back-pressure: before finishing step t, wait g_prog[CONS] >= t-5 (ring 8).
// ---------------------------------------------------------------------------
template <int H, int HIN, int NWH, int XGMODE, int OWN, int PROD, int CONS,
          bool WRITE_YS, int ZRING = 0>
__device__ __forceinline__ void run_layer(
        int b,
        const float* __restrict__ Whh,
        const float* __restrict__ Wih,
        const float* __restrict__ bih,
        const float* __restrict__ bhh,
        const float* __restrict__ xs) {
    constexpr int NWI  = 16 - NWH;
    constexpr int SL_H = H / NWH;
    constexpr int SL_I = (HIN > 0) ? (HIN / (NWI > 0 ? NWI : 1)) : 2;
    constexpr int NQH  = SL_H / 2;
    constexpr int NQI  = (HIN > 0) ? SL_I / 2 : 0;
    constexpr int NQMAX = (NQI > NQH) ? NQI : NQH;

    const int tid  = threadIdx.x;
    const int wid  = tid >> 5;
    const int lane = tid & 31;
    const int gate = lane >> 3;
    const int unit = lane & 7;
    const int grow = gate * H + b * 8 + unit;
    const bool is_h = (wid < NWH);

    // weights in registers (f32x2 packed)
    ull wq[NQMAX];
    if (is_h) {
        const ull* wp = (const ull*)(Whh + (size_t)grow * H + wid * SL_H);
#pragma unroll
        for (int i = 0; i < NQH; ++i) wq[i] = wp[i];
    } else {
        if constexpr (HIN > 0) {
            const ull* wp = (const ull*)
                (Wih + (size_t)grow * HIN + (wid - NWH) * SL_I);
#pragma unroll
            for (int i = 0; i < NQI; ++i) wq[i] = wp[i];
        }
    }

    __shared__ __align__(16) float h_s[H + ((HIN > 0) ? HIN : 0)];
    __shared__ float red[16][32];

    float c = 0.0f;
    float xconst = 0.0f;   // bias (mode 0/1) or full const input row (mode 2)
    float xw = 0.0f;       // e1 scalar input weight
    if (wid == 0) {
        if constexpr (XGMODE == 0) {
            xconst = bih[grow] + bhh[grow];
        } else if constexpr (XGMODE == 1) {
            xconst = bih[grow] + bhh[grow];
            xw = Wih[grow];                      // Wih is [4H, 1]
        } else {
            // prologue dot: xconst = b + Wih[grow,:] . z  (z = ring ZRING slot0)
            float s = bih[grow] + bhh[grow];
            const float* w = Wih + (size_t)grow * 128;
#pragma unroll 8
            for (int k = 0; k < 128; ++k) {
                float z = __uint_as_float((unsigned)g_ring[ZRING][0][k]);
                s += z * w[k];
            }
            xconst = s;
        }
    }

    // publish h0 = 0 with epoch 0 into slot 0
    if (wid == 0 && lane < 8) {
        *(volatile ull*)&g_ring[OWN][0][b * 8 + lane] = 0ull;
    }

    for (int t = 0; t < T_SEQ; ++t) {
        float xval = xconst;
        if (wid == 0) {
            if constexpr (XGMODE == 1)
                xval = fmaf(__ldg(xs + t), xw, xconst);
        }

        // back-pressure on consumer layer progress (ring depth 8)
        if constexpr (CONS >= 0) {
            if (wid == 15 && lane == 31) {
                volatile int* pp = &g_prog[CONS];
                while (*pp < t - 5) { __nanosleep(100); }
            }
        }

        // poll + stage this warp's slice
        if (is_h) {
            // own-h: tight poll (critical cycle)
            const volatile ull* src = &g_ring[OWN][t & 7][wid * SL_H];
#pragma unroll
            for (int j = 0; j < SL_H; j += 32) {
                int idx = j + lane;
                if (idx < SL_H) {
                    ull v;
                    do { v = src[idx]; } while ((unsigned)(v >> 32) != (unsigned)t);
                    h_s[wid * SL_H + idx] = __uint_as_float((unsigned)v);
                }
            }
        } else {
            if constexpr (HIN > 0) {
                // producer input: backoff poll (off critical cycle)
                const volatile ull* src =
                    &g_ring[PROD][(t + 1) & 7][(wid - NWH) * SL_I];
#pragma unroll
                for (int j = 0; j < SL_I; j += 32) {
                    int idx = j + lane;
                    if (idx < SL_I) {
                        ull v = src[idx];
                        while ((unsigned)(v >> 32) != (unsigned)(t + 1)) {
                            __nanosleep(40);
                            v = src[idx];
                        }
                        h_s[H + (wid - NWH) * SL_I + idx] =
                            __uint_as_float((unsigned)v);
                    }
                }
            }
        }
        __syncthreads();   // sync_A

        // matvec partial over this warp's slice
        float part = 0.0f;
        if (is_h) {
            const ull* hq = (const ull*)&h_s[wid * SL_H];
            ull a0 = 0ull, a1 = 0ull;
#pragma unroll
            for (int i = 0; i < NQH; i += 2) {
                fma2(a0, wq[i], hq[i]);
                if (i + 1 < NQH) fma2(a1, wq[i + 1], hq[i + 1]);
            }
            part = f32x2_sum(a0) + f32x2_sum(a1);
        } else {
            if constexpr (HIN > 0) {
                const ull* hq = (const ull*)&h_s[H + (wid - NWH) * SL_I];
                ull a0 = 0ull, a1 = 0ull;
#pragma unroll
                for (int i = 0; i < NQI; i += 2) {
                    fma2(a0, wq[i], hq[i]);
                    if (i + 1 < NQI) fma2(a1, wq[i + 1], hq[i + 1]);
                }
                part = f32x2_sum(a0) + f32x2_sum(a1);
            }
        }
        red[wid][lane] = part;
        __syncthreads();   // sync_B

        if (wid == 0) {
            float s0 = xval, s1 = 0.0f, s2 = 0.0f, s3 = 0.0f;
#pragma unroll
            for (int k = 0; k < 16; k += 4) {
                s0 += red[k][lane];
                s1 += red[k + 1][lane];
                s2 += red[k + 2][lane];
                s3 += red[k + 3][lane];
            }
            float s = (s0 + s1) + (s2 + s3);

            // gate 2: tanh(s); others: sigmoid(s) = 0.5*tanh(0.5 s) + 0.5
            bool isg = (gate == 2);
            float sa = isg ? s : 0.5f * s;
            float tv = tanh_a(sa);
            float act = isg ? tv : fmaf(0.5f, tv, 0.5f);

            float i_ = __shfl_sync(0xffffffffu, act, unit);
            float f_ = __shfl_sync(0xffffffffu, act, 8 + unit);
            float g_ = __shfl_sync(0xffffffffu, act, 16 + unit);
            float o_ = __shfl_sync(0xffffffffu, act, 24 + unit);

            if (lane < 8) {
                c = f_ * c + i_ * g_;
                float h = o_ * tanh_a(c);
                ull word = (((ull)(unsigned)(t + 1)) << 32)
                         | (ull)__float_as_uint(h);
                *(volatile ull*)&g_ring[OWN][(t + 1) & 7][b * 8 + lane] = word;
                if (WRITE_YS)
                    g_ys[(size_t)t * 512 + b * 8 + lane] = h;
            }
            if (b == 0 && lane == 8) {
                *(volatile int*)&g_prog[OWN] = t + 1;
            }
        }
        // non-warp-0 warps run ahead into the next step's poll.
    }
}

// ---------------------------------------------------------------------------
// Fused encoder: e1 (64 CTAs), e2 (32), e3 (16) -- 112 CTAs, single wave.
// ---------------------------------------------------------------------------
__global__ void __launch_bounds__(512, 1) encoder_kernel(
        const float* __restrict__ x,
        const float* __restrict__ e1_Whh, const float* __restrict__ e1_Wih,
        const float* __restrict__ e1_bih, const float* __restrict__ e1_bhh,
        const float* __restrict__ e2_Whh, const float* __restrict__ e2_Wih,
        const float* __restrict__ e2_bih, const float* __restrict__ e2_bhh,
        const float* __restrict__ e3_Whh, const float* __restrict__ e3_Wih,
        const float* __restrict__ e3_bih, const float* __restrict__ e3_bhh) {
    int bx = blockIdx.x;
    if (bx < 64) {
        run_layer<512, 0, 16, /*XG*/1, /*OWN*/0, /*PROD*/0, /*CONS*/1, false>(
            bx, e1_Whh, e1_Wih, e1_bih, e1_bhh, x);
    } else if (bx < 96) {
        run_layer<256, 512, 8, 0, 1, 0, 2, false>(
            bx - 64, e2_Whh, e2_Wih, e2_bih, e2_bhh, nullptr);
    } else {
        run_layer<128, 256, 8, 0, 2, 1, -1, false>(
            bx - 96, e3_Whh, e3_Wih, e3_bih, e3_bhh, nullptr);
    }
}

// ---------------------------------------------------------------------------
// Fused decoder: d1 (16 CTAs), d2 (32), d3 (64) -- 112 CTAs, single wave.
// ---------------------------------------------------------------------------
__global__ void __launch_bounds__(512, 1) decoder_kernel(
        const float* __restrict__ d1_Whh, const float* __restrict__ d1_Wih,
        const float* __restrict__ d1_bih, const float* __restrict__ d1_bhh,
        const float* __restrict__ d2_Whh, const float* __restrict__ d2_Wih,
        const float* __restrict__ d2_bih, const float* __restrict__ d2_bhh,
        const float* __restrict__ d3_Whh, const float* __restrict__ d3_Wih,
        const float* __restrict__ d3_bih, const float* __restrict__ d3_bhh) {
    int bx = blockIdx.x;
    if (bx < 16) {
        // d1: constant input row from e3's final h (ring 2, slot 0)
        run_layer<128, 0, 16, /*XG*/2, /*OWN*/3, /*PROD*/3, /*CONS*/4, false,
                  /*ZRING*/2>(
            bx, d1_Whh, d1_Wih, d1_bih, d1_bhh, nullptr);
    } else if (bx < 48) {
        run_layer<256, 128, 8, 0, 4, 3, 5, false>(
            bx - 16, d2_Whh, d2_Wih, d2_bih, d2_bhh, nullptr);
    } else {
        run_layer<512, 256, 8, 0, 5, 4, -1, true>(
            bx - 48, d3_Whh, d3_Wih, d3_bih, d3_bhh, nullptr);
    }
}

// ---------------------------------------------------------------------------
// Final projection: out[t] = ys_d3[t,:] . out_W + out_b
// ---------------------------------------------------------------------------
__global__ void out_proj_kernel(const float* __restrict__ w,
                                const float* __restrict__ bias,
                                float* __restrict__ out) {
    int gtid = blockIdx.x * blockDim.x + threadIdx.x;
    int warp = gtid >> 5;
    int lane = threadIdx.x & 31;
    if (warp >= T_SEQ) return;
    const float* y = g_ys + (size_t)warp * 512;
    float s = 0.0f;
#pragma unroll
    for (int j = 0; j < 16; ++j) {
        s += y[lane + 32 * j] * w[lane + 32 * j];
    }
#pragma unroll
    for (int off = 16; off > 0; off >>= 1)
        s += __shfl_down_sync(0xffffffffu, s, off);
    if (lane == 0) out[warp] = s + bias[0];
}

// ---------------------------------------------------------------------------
extern "C" void kernel_launch(void* const* d_in, const int* in_sizes, int n_in,
                              void* d_out, int out_size) {
    const float* x       = (const float*)d_in[0];
    const float* e1_Wih  = (const float*)d_in[1];
    const float* e1_Whh  = (const float*)d_in[2];
    const float* e1_bih  = (const float*)d_in[3];
    const float* e1_bhh  = (const float*)d_in[4];
    const float* e2_Wih  = (const float*)d_in[5];
    const float* e2_Whh  = (const float*)d_in[6];
    const float* e2_bih  = (const float*)d_in[7];
    const float* e2_bhh  = (const float*)d_in[8];
    const float* e3_Wih  = (const float*)d_in[9];
    const float* e3_Whh  = (const float*)d_in[10];
    const float* e3_bih  = (const float*)d_in[11];
    const float* e3_bhh  = (const float*)d_in[12];
    const float* d1_Wih  = (const float*)d_in[13];
    const float* d1_Whh  = (const float*)d_in[14];
    const float* d1_bih  = (const float*)d_in[15];
    const float* d1_bhh  = (const float*)d_in[16];
    const float* d2_Wih  = (const float*)d_in[17];
    const float* d2_Whh  = (const float*)d_in[18];
    const float* d2_bih  = (const float*)d_in[19];
    const float* d2_bhh  = (const float*)d_in[20];
    const float* d3_Wih  = (const float*)d_in[21];
    const float* d3_Whh  = (const float*)d_in[22];
    const float* d3_bih  = (const float*)d_in[23];
    const float* d3_bhh  = (const float*)d_in[24];
    const float* out_W   = (const float*)d_in[25];
    const float* out_b   = (const float*)d_in[26];
    float* out = (float*)d_out;

    reset_prog_kernel<<<1, 32>>>();

    encoder_kernel<<<112, 512>>>(x,
                                 e1_Whh, e1_Wih, e1_bih, e1_bhh,
                                 e2_Whh, e2_Wih, e2_bih, e2_bhh,
                                 e3_Whh, e3_Wih, e3_bih, e3_bhh);

    decoder_kernel<<<112, 512>>>(d1_Whh, d1_Wih, d1_bih, d1_bhh,
                                 d2_Whh, d2_Wih, d2_bih, d2_bhh,
                                 d3_Whh, d3_Wih, d3_bih, d3_bhh);

    out_proj_kernel<<<(T_SEQ * 32) / 256, 256>>>(out_W, out_b, out);
}